// round 12
// baseline (speedup 1.0000x reference)
#include <cuda_runtime.h>
#include <cuda_fp16.h>
#include <cstdint>

// ---------------------------------------------------------------------------
// MMD loss via mma.sync fp16 gram (fp32 accum) + fused half2 gaussian epilogue
//   loss = (1/ns^2) * sum_{i,j} s_i s_j K_ij
//   K_ij = u + u^2 + u^4 + u^8 + u^16,  u = 2^(-l2_ij*c4), c4 = log2e/(bw*16)
//   l2_ij = sq_i + sq_j - 2 g_ij ; bandwidth via O(nD) identity.
// Scale sqrt(2*c4) folded into fp16 inputs -> accumulators are 2*c4*gram.
// Gaussian collapse in half2; PARTIAL SUMS ACCUMULATED IN FP32 (R11's fp16
// running-sum accumulation was the 3e-3 failure: ulp grows with magnitude).
// Symmetry: triangular grid (2080 CTAs), off-diagonal tiles weight 2.
// Launches: init -> prep -> permute(computes c4 per block) -> mmd(writes out).
// ---------------------------------------------------------------------------

#define NS     4096
#define DDIM   256
#define NTOT   8192
#define BM     128
#define BKC    64
#define NCHUNK (DDIM / BKC)     // 4
#define NTILES (NTOT / BM)      // 64
#define NBLK   (NTILES * (NTILES + 1) / 2)   // 2080

#define ASTG   16384            // A stage: 8 rowblocks x 4 ksteps x 512B
#define BSTG   16384            // B stage: 16 colblocks x 4 ksteps x 256B

// smem byte offsets (3 stages each)
#define SM_A0   0
#define SM_B0   (3 * ASTG)      // 49152
#define SM_SQI  (6 * ASTG)      // 98304
#define SM_SQJ  (SM_SQI + 512)
#define SM_RED  (SM_SQI + 1024)
#define SMEM_BYTES (SM_SQI + 2048)   // 100352 -> 2 CTAs/SM

__device__ __half   g_convA[NTOT * DDIM];  // A-fragment order, scaled, 4 MB
__device__ __half   g_convB[NTOT * DDIM];  // B-fragment order, scaled, 4 MB
__device__ float    g_sq[NTOT];
__device__ float    g_colsum[DDIM];
__device__ double   g_ssum;
__device__ double   g_acc;
__device__ float    g_c4;
__device__ unsigned g_done;

// ---------------------------------------------------------------------------
__device__ __forceinline__ float ex2f(float x) {
    float r; asm("ex2.approx.ftz.f32 %0, %1;" : "=f"(r) : "f"(x)); return r;
}
__device__ __forceinline__ uint32_t smem_u32(const void* p) {
    uint32_t a;
    asm("{ .reg .u64 t; cvta.to.shared.u64 t, %1; cvt.u32.u64 %0, t; }"
        : "=r"(a) : "l"(p));
    return a;
}
__device__ __forceinline__ void cp16(uint32_t dst, const void* src) {
    asm volatile("cp.async.cg.shared.global [%0], [%1], 16;"
                 :: "r"(dst), "l"(src));
}
__device__ __forceinline__ void cp_commit() {
    asm volatile("cp.async.commit_group;" ::: "memory");
}
template <int N>
__device__ __forceinline__ void cp_wait() {
    asm volatile("cp.async.wait_group %0;" :: "n"(N) : "memory");
}
__device__ __forceinline__ void mma_f16(float c[4], const uint4 a,
                                        const uint2 b) {
    asm volatile(
        "mma.sync.aligned.m16n8k16.row.col.f32.f16.f16.f32 "
        "{%0,%1,%2,%3},{%4,%5,%6,%7},{%8,%9},{%0,%1,%2,%3};"
        : "+f"(c[0]), "+f"(c[1]), "+f"(c[2]), "+f"(c[3])
        : "r"(a.x), "r"(a.y), "r"(a.z), "r"(a.w), "r"(b.x), "r"(b.y));
}
__device__ __forceinline__ const float* srow(const float* __restrict__ src,
                                             const float* __restrict__ tgt,
                                             int row) {
    return (row < NS) ? (src + (size_t)row * DDIM)
                      : (tgt + (size_t)(row - NS) * DDIM);
}
__device__ __forceinline__ uint32_t pack_h2(float lo, float hi) {
    __half2 h = __floats2half2_rn(lo, hi);
    return *(uint32_t*)&h;
}

// ---------------------------------------------------------------------------
__global__ void init_kernel() {
    int t = threadIdx.x;
    if (t < DDIM) g_colsum[t] = 0.0f;
    if (t == 0) { g_acc = 0.0; g_ssum = 0.0; g_done = 0u; }
}

// prep: sumsq per row + colsums + total sumsq (reads raw fp32 src/tgt).
__global__ void prep_kernel(const float* __restrict__ src,
                            const float* __restrict__ tgt) {
    const int tid  = threadIdx.x;
    const int w    = tid >> 5;
    const int lane = tid & 31;
    const int b    = blockIdx.x;
    const float* base = (b < 128) ? (src + (size_t)b * 32 * DDIM)
                                  : (tgt + (size_t)(b - 128) * 32 * DDIM);
    __shared__ float wsum[8];

    float mysq = 0.0f;
    #pragma unroll
    for (int it = 0; it < 4; it++) {
        int r = it * 8 + w;
        const float* p = base + (size_t)r * DDIM;
        float4 a = *(const float4*)(p + lane * 8);
        float4 c = *(const float4*)(p + lane * 8 + 4);
        float s = a.x*a.x + a.y*a.y + a.z*a.z + a.w*a.w
                + c.x*c.x + c.y*c.y + c.z*c.z + c.w*c.w;
        #pragma unroll
        for (int o = 16; o > 0; o >>= 1) s += __shfl_xor_sync(0xFFFFFFFFu, s, o);
        if (lane == 0) { g_sq[b * 32 + r] = s; mysq += s; }
    }
    if (lane == 0) wsum[w] = mysq;

    float cs = 0.0f;
    #pragma unroll 8
    for (int r = 0; r < 32; r++) cs += base[(size_t)r * DDIM + tid];
    atomicAdd(&g_colsum[tid], cs);

    __syncthreads();
    if (tid == 0) {
        float tot = 0.0f;
        #pragma unroll
        for (int i = 0; i < 8; i++) tot += wsum[i];
        atomicAdd(&g_ssum, (double)tot);
    }
}

// permute: compute c4 (every block, redundantly), then build scaled fp16
// fragment-ordered copies. blocks [0,1024): A. blocks [1024,3072): B.
__global__ void permute_kernel(const float* __restrict__ src,
                               const float* __restrict__ tgt) {
    __shared__ float  s_scale;
    __shared__ double wred[8];
    const int tid  = threadIdx.x;
    const int w    = tid >> 5;
    const int lane = tid & 31;

    {   // bandwidth -> c4 -> scale
        float c = g_colsum[tid];
        double v = (double)c * (double)c;
        #pragma unroll
        for (int o = 16; o > 0; o >>= 1)
            v += __shfl_xor_sync(0xFFFFFFFFu, v, o);
        if (lane == 0) wred[w] = v;
        __syncthreads();
        if (tid == 0) {
            double V = 0.0;
            #pragma unroll
            for (int i = 0; i < 8; i++) V += wred[i];
            double S      = g_ssum;
            double n      = (double)NTOT;
            double sum_l2 = 2.0 * n * S - 2.0 * V;
            double bw     = sum_l2 / (n * n - n);
            bw /= 4.0;                               // KERNEL_MUL^(NUM//2)
            float c4 = (float)(1.4426950408889634 / (bw * 16.0));
            s_scale = sqrtf(2.0f * c4);
            if (blockIdx.x == 0) g_c4 = c4;
        }
        __syncthreads();
    }
    const float sc = s_scale;

    if (blockIdx.x < 1024) {
        int o    = blockIdx.x * 256 + tid;          // 16B unit index
        int RB   = o >> 9;
        int rem  = o & 511;
        int KS   = rem >> 5;
        int ln   = rem & 31;
        int g    = ln >> 2;
        int t4   = ln & 3;
        int r    = RB * 16 + g;
        int k    = KS * 16 + t4 * 2;
        const float* p0 = srow(src, tgt, r);
        const float* p1 = srow(src, tgt, r + 8);
        uint4 v;
        v.x = pack_h2(p0[k] * sc,     p0[k + 1] * sc);
        v.y = pack_h2(p1[k] * sc,     p1[k + 1] * sc);
        v.z = pack_h2(p0[k + 8] * sc, p0[k + 9] * sc);
        v.w = pack_h2(p1[k + 8] * sc, p1[k + 9] * sc);
        *(uint4*)((char*)g_convA + (size_t)o * 16) = v;
    } else {
        int o    = (blockIdx.x - 1024) * 256 + tid; // 8B unit index
        int CB   = o >> 9;
        int rem  = o & 511;
        int KS   = rem >> 5;
        int ln   = rem & 31;
        int g    = ln >> 2;
        int t4   = ln & 3;
        int c    = CB * 8 + g;
        int k    = KS * 16 + t4 * 2;
        const float* p = srow(src, tgt, c);
        uint2 v;
        v.x = pack_h2(p[k] * sc,     p[k + 1] * sc);
        v.y = pack_h2(p[k + 8] * sc, p[k + 9] * sc);
        *(uint2*)((char*)g_convB + (size_t)o * 8) = v;
    }
}

// ---------------------------------------------------------------------------
// Fused tile kernel. Accumulators = 2*c4*gram (scale folded into inputs).
__global__ void __launch_bounds__(256, 2)
mmd_kernel(float* __restrict__ out) {
    // triangular decode: idx -> (ti, tj), ti <= tj
    int idx = blockIdx.x;
    int ti = (int)((129.0 - sqrt(129.0 * 129.0 - 8.0 * (double)idx)) * 0.5);
    if (ti > NTILES - 1) ti = NTILES - 1;
    while (ti > 0 && idx < ti * NTILES - ti * (ti - 1) / 2) ti--;
    while (idx >= (ti + 1) * NTILES - (ti + 1) * ti / 2) ti++;
    const int tj = ti + (idx - (ti * NTILES - ti * (ti - 1) / 2));

    extern __shared__ char smem[];
    const uint32_t sbase = smem_u32(smem);
    float* sqi = (float*)(smem + SM_SQI);   // holds sq * c4
    float* sqj = (float*)(smem + SM_SQJ);
    float* red = (float*)(smem + SM_RED);

    const int tid  = threadIdx.x;
    const int wid  = tid >> 5;
    const int lane = tid & 31;
    const int g    = lane >> 2;
    const int t4   = lane & 3;
    const int wm   = wid & 1;
    const int wn   = wid >> 1;

    const int i0 = ti * BM;
    const int j0 = tj * BM;
    const int Rb = ti * 8;
    const int Cb = tj * 16;

    const float c4 = g_c4;
    if (tid < 128) sqi[tid]       = g_sq[i0 + tid] * c4;
    else           sqj[tid - 128] = g_sq[j0 + tid - 128] * c4;

    #pragma unroll
    for (int c = 0; c < 2; c++) {
        #pragma unroll
        for (int l = 0; l < 4; l++) {
            int ia = tid + l * 256;
            cp16(sbase + SM_A0 + c * ASTG + ia * 16,
                 (const char*)g_convA + (size_t)(Rb + (ia >> 7)) * 8192
                     + (c * 4 + ((ia >> 5) & 3)) * 512 + (ia & 31) * 16);
            cp16(sbase + SM_B0 + c * BSTG + ia * 16,
                 (const char*)g_convB + (size_t)(Cb + (ia >> 6)) * 4096
                     + (c * 4 + ((ia >> 4) & 3)) * 256 + (ia & 15) * 16);
        }
        cp_commit();
    }

    float acc[4][4][4];
    #pragma unroll
    for (int a = 0; a < 4; a++)
        #pragma unroll
        for (int b = 0; b < 4; b++)
            #pragma unroll
            for (int f = 0; f < 4; f++) acc[a][b][f] = 0.0f;

    int st_c = 0, st_p = 2;
    #pragma unroll 1
    for (int c = 0; c < NCHUNK; c++) {
        if (c + 2 < NCHUNK) {
            const int cc = c + 2;
            #pragma unroll
            for (int l = 0; l < 4; l++) {
                int ia = tid + l * 256;
                cp16(sbase + SM_A0 + st_p * ASTG + ia * 16,
                     (const char*)g_convA + (size_t)(Rb + (ia >> 7)) * 8192
                         + (cc * 4 + ((ia >> 5) & 3)) * 512 + (ia & 31) * 16);
                cp16(sbase + SM_B0 + st_p * BSTG + ia * 16,
                     (const char*)g_convB + (size_t)(Cb + (ia >> 6)) * 4096
                         + (cc * 4 + ((ia >> 4) & 3)) * 256 + (ia & 15) * 16);
            }
            cp_commit();
            cp_wait<2>();
        } else if (c + 1 < NCHUNK) {
            cp_wait<1>();
        } else {
            cp_wait<0>();
        }
        __syncthreads();

        const char* As = smem + SM_A0 + st_c * ASTG;
        const char* Bs = smem + SM_B0 + st_c * BSTG;

        #pragma unroll
        for (int s = 0; s < 4; s++) {
            uint4 af[4];
            uint2 bf[4];
            #pragma unroll
            for (int ma = 0; ma < 4; ma++)
                af[ma] = *(const uint4*)(As + (wm * 4 + ma) * 2048 + s * 512
                                            + lane * 16);
            #pragma unroll
            for (int nb = 0; nb < 4; nb++)
                bf[nb] = *(const uint2*)(Bs + (wn * 4 + nb) * 1024 + s * 256
                                            + lane * 8);
            #pragma unroll
            for (int ma = 0; ma < 4; ma++)
                #pragma unroll
                for (int nb = 0; nb < 4; nb++)
                    mma_f16(acc[ma][nb], af[ma], bf[nb]);
        }
        __syncthreads();

        st_c = (st_c == 2) ? 0 : st_c + 1;
        st_p = (st_p == 2) ? 0 : st_p + 1;
    }

    // --- epilogue: arg = acc - si*c4 - sj*c4 ; K via half2 collapse,
    //     per-pair K converted to fp32 before accumulation (R11 fix). ---
    float sic[4][2], sjc[4][2];
    #pragma unroll
    for (int ma = 0; ma < 4; ma++) {
        sic[ma][0] = sqi[wm * 64 + ma * 16 + g];
        sic[ma][1] = sqi[wm * 64 + ma * 16 + g + 8];
    }
    #pragma unroll
    for (int nb = 0; nb < 4; nb++) {
        sjc[nb][0] = sqj[wn * 32 + nb * 8 + 2 * t4];
        sjc[nb][1] = sqj[wn * 32 + nb * 8 + 2 * t4 + 1];
    }

    float part = 0.0f;
    #pragma unroll
    for (int ma = 0; ma < 4; ma++) {
        #pragma unroll
        for (int nb = 0; nb < 4; nb++) {
            const float* a = acc[ma][nb];
            float a0 = a[0] - sic[ma][0] - sjc[nb][0];
            float a1 = a[1] - sic[ma][0] - sjc[nb][1];
            float a2 = a[2] - sic[ma][1] - sjc[nb][0];
            float a3 = a[3] - sic[ma][1] - sjc[nb][1];
            __half2 h01 = __floats2half2_rn(ex2f(a0), ex2f(a1));
            __half2 h23 = __floats2half2_rn(ex2f(a2), ex2f(a3));
            __half2 p2  = __hmul2(h01, h01);
            __half2 p4  = __hmul2(p2, p2);
            __half2 p8  = __hmul2(p4, p4);
            __half2 p16 = __hmul2(p8, p8);
            __half2 k01 = __hadd2(__hadd2(h01, p2),
                                  __hadd2(__hadd2(p4, p8), p16));
            __half2 q2  = __hmul2(h23, h23);
            __half2 q4  = __hmul2(q2, q2);
            __half2 q8  = __hmul2(q4, q4);
            __half2 q16 = __hmul2(q8, q8);
            __half2 k23 = __hadd2(__hadd2(h23, q2),
                                  __hadd2(__hadd2(q4, q8), q16));
            float2 f01 = __half22float2(k01);
            float2 f23 = __half22float2(k23);
            part += (f01.x + f01.y) + (f23.x + f23.y);
        }
    }

    float w  = (ti == tj) ? 1.0f : 2.0f;
    float sg = ((ti < NTILES / 2) == (tj < NTILES / 2)) ? 1.0f : -1.0f;
    part *= w * sg;

    red[tid] = part;
    __syncthreads();
    #pragma unroll
    for (int s = 128; s > 0; s >>= 1) {
        if (tid < s) red[tid] += red[tid + s];
        __syncthreads();
    }
    if (tid == 0) {
        atomicAdd(&g_acc, (double)red[0]);
        __threadfence();
        unsigned old = atomicAdd(&g_done, 1u);
        if (old == NBLK - 1) {
            double v = atomicAdd(&g_acc, 0.0);   // atomic read after fence
            out[0] = (float)(v / ((double)NS * (double)NS));
        }
    }
}

// ---------------------------------------------------------------------------
extern "C" void kernel_launch(void* const* d_in, const int* in_sizes, int n_in,
                              void* d_out, int out_size) {
    const float* src = (const float*)d_in[0];
    const float* tgt = (const float*)d_in[1];
    float* out = (float*)d_out;

    cudaFuncSetAttribute(mmd_kernel,
                         cudaFuncAttributeMaxDynamicSharedMemorySize, SMEM_BYTES);

    init_kernel<<<1, 256>>>();
    prep_kernel<<<256, 256>>>(src, tgt);
    permute_kernel<<<3072, 256>>>(src, tgt);
    mmd_kernel<<<NBLK, 256, SMEM_BYTES>>>(out);
}